// round 8
// baseline (speedup 1.0000x reference)
#include <cuda_runtime.h>
#include <cuda_fp16.h>
#include <cstdint>
#include <math.h>

// Static problem shape
#define BB 32
#define TT 512
#define DD 512
#define TS 2304          // target_length - 1

#define BM 128           // t tile
#define BN 256           // d tile
#define BK 16            // k per chunk (8 kp words)
#define NCHUNK (TT/BK)   // 32

// SMEM rows: 8 kp words (32B) padded to 12 words (48B) -> ldmatrix conflict-free
#define RSTRB 48
#define ASZ (BM*RSTRB)       // 6144
#define BSZ (BN*RSTRB)       // 12288
#define STG (ASZ+BSZ)        // 18432
#define NST 3
#define DYN_SMEM (NST*STG)   // 55296

// Device scratch
__device__ float    g_sig[BB*TT];
__device__ float    g_center[BB*TT];
__device__ int      g_shift[BB*TT];
__device__ int      g_len[BB*TT];
__device__ float    g_scale[BB*TS];
// W precomputed fp16, k-pair packed: word(b,t,kp) = half2(w[2kp], w[2kp+1]), scale folded
__device__ uint32_t g_w[(size_t)BB*TS*(TT/2)];     // 75.5 MB
// xs transposed+packed: word(b,d,ip) = half2(xs[2ip][d], xs[2ip+1][d])
__device__ uint32_t g_xsT[(size_t)BB*DD*(TT/2)];   // 16.8 MB

__device__ __forceinline__ void mma_fp16(float* c, const uint32_t* a, const uint32_t* b) {
    asm volatile(
        "mma.sync.aligned.m16n8k16.row.col.f32.f16.f16.f32 "
        "{%0,%1,%2,%3}, {%4,%5,%6,%7}, {%8,%9}, {%0,%1,%2,%3};"
        : "+f"(c[0]), "+f"(c[1]), "+f"(c[2]), "+f"(c[3])
        : "r"(a[0]), "r"(a[1]), "r"(a[2]), "r"(a[3]), "r"(b[0]), "r"(b[1]));
}
__device__ __forceinline__ void ldm_x4(uint32_t* r, uint32_t addr) {
    asm volatile("ldmatrix.sync.aligned.m8n8.x4.shared.b16 {%0,%1,%2,%3}, [%4];"
                 : "=r"(r[0]), "=r"(r[1]), "=r"(r[2]), "=r"(r[3]) : "r"(addr));
}
__device__ __forceinline__ uint32_t smem_u32(const void* p) {
    uint32_t a;
    asm("{ .reg .u64 t; cvta.to.shared.u64 t, %1; cvt.u32.u64 %0, t; }" : "=r"(a) : "l"(p));
    return a;
}
__device__ __forceinline__ uint32_t pack_h2(float lo, float hi) {
    __half2 h = __floats2half2_rn(lo, hi);
    return *(uint32_t*)&h;
}

// ---------------------------------------------------------------------------
// Kernel 1: prep — cumsum(ds), center, sig = softplus(sigma)
// ---------------------------------------------------------------------------
__global__ void lr_prep_kernel(const int* __restrict__ ds,
                               const float* __restrict__ sigma) {
    __shared__ int s[TT];
    int b = blockIdx.x, t = threadIdx.x;
    int d = ds[b*TT + t];
    s[t] = d;
    __syncthreads();
    for (int off = 1; off < TT; off <<= 1) {
        int v = (t >= off) ? s[t - off] : 0;
        __syncthreads();
        s[t] += v;
        __syncthreads();
    }
    int len = s[t], sh = len - d, idx = b*TT + t;
    g_len[idx] = len;
    g_shift[idx] = sh;
    g_center[idx] = 0.5f * (float)d + (float)sh;
    float x = sigma[idx];
    g_sig[idx] = (x > 20.f) ? x : log1pf(expf(x));
}

// ---------------------------------------------------------------------------
// Kernel 2: scale[b,t] = row_mass / max(den, 1e-12)
// ---------------------------------------------------------------------------
__global__ void lr_scale_kernel() {
    int warp = (blockIdx.x * blockDim.x + threadIdx.x) >> 5;
    int lane = threadIdx.x & 31;
    if (warp >= BB * TS) return;
    int b = warp / TS, t = warp % TS;
    float tr = (float)(t + 1);
    const float* sg = g_sig + b*TT;
    const float* ce = g_center + b*TT;
    const int* shp = g_shift + b*TT;
    const int* lnp = g_len + b*TT;
    float den = 0.f; int mass = 0;
    #pragma unroll 4
    for (int i = lane; i < TT; i += 32) {
        float s = sg[i], dl = tr - ce[i];
        den += __expf(-0.5f * dl * dl * s * s) * s;
        mass += (t >= shp[i] && t < lnp[i]) ? 1 : 0;
    }
    #pragma unroll
    for (int o = 16; o > 0; o >>= 1) {
        den  += __shfl_down_sync(0xffffffffu, den, o);
        mass += __shfl_down_sync(0xffffffffu, mass, o);
    }
    if (lane == 0) g_scale[warp] = (float)mass / fmaxf(den, 1e-12f);
}

// ---------------------------------------------------------------------------
// Kernel 3: W generation -> g_w, fp16 k-pair packed, scale folded
// block: 256 thr = 4 t-rows x 64 lanes; each thread 4 words (8 exps)
// ---------------------------------------------------------------------------
__global__ void lr_wgen_kernel() {
    __shared__ float sS[TT], sC[TT];
    int b = blockIdx.y;
    int t = blockIdx.x * 4 + (threadIdx.x >> 6);
    int l = threadIdx.x & 63;
    for (int i = threadIdx.x; i < TT; i += 256) {
        sS[i] = g_sig[b*TT + i];
        sC[i] = g_center[b*TT + i];
    }
    __syncthreads();
    float sc = g_scale[b*TS + t];
    float tr = (float)(t + 1);
    uint32_t w[4];
    #pragma unroll
    for (int j = 0; j < 4; j++) {
        int k = (l*4 + j) * 2;
        float s0 = sS[k],   c0 = sC[k],   dl0 = tr - c0;
        float s1 = sS[k+1], c1 = sC[k+1], dl1 = tr - c1;
        float e0 = __expf(-0.5f * s0 * s0 * dl0 * dl0) * s0 * sc;
        float e1 = __expf(-0.5f * s1 * s1 * dl1 * dl1) * s1 * sc;
        w[j] = pack_h2(e0, e1);
    }
    *(uint4*)&g_w[((size_t)b*TS + t) * (TT/2) + l*4] = *(uint4*)w;
}

// ---------------------------------------------------------------------------
// Kernel 4: xs -> g_xsT  (transpose to d-major, fp16 k-pair packed)
// ---------------------------------------------------------------------------
__global__ void lr_cvtT_kernel(const float* __restrict__ xs) {
    __shared__ float tile[32][33];
    int b = blockIdx.z;
    int dblk = blockIdx.x * 32, iblk = blockIdx.y * 32;
    int tx = threadIdx.x, ty = threadIdx.y;     // 32 x 8
    #pragma unroll
    for (int j = 0; j < 32; j += 8)
        tile[ty + j][tx] = xs[((size_t)(b*TT) + iblk + ty + j) * DD + dblk + tx];
    __syncthreads();
    int q = ty * 32 + tx;   // 0..255
    #pragma unroll
    for (int j = 0; j < 2; j++) {
        int v = q + 256 * j;          // 0..511
        int dl = v >> 4;              // 0..31
        int ip = v & 15;              // 0..15
        uint32_t w = pack_h2(tile[2*ip][dl], tile[2*ip + 1][dl]);
        g_xsT[((size_t)(b*DD) + dblk + dl) * (TT/2) + iblk/2 + ip] = w;
    }
}

// ---------------------------------------------------------------------------
// Kernel 5: GEMM. CTA 128x256, 8 warps (2x4), warp 64x64.
// A/B both cp.async from gmem; fragments via ldmatrix.x4; 3-stage pipeline.
// ---------------------------------------------------------------------------
__global__ __launch_bounds__(256, 1)
void lr_gemm_mma(float* __restrict__ out) {
    extern __shared__ char sm[];
    uint32_t sbase = smem_u32(sm);

    int tid = threadIdx.x;
    int wid = tid >> 5, lane = tid & 31;
    int g = lane >> 2, tig = lane & 3;
    int wm = wid >> 2;          // 0..1
    int wn = wid & 3;           // 0..3
    int b = blockIdx.z, t0 = blockIdx.y * BM, d0 = blockIdx.x * BN;

    const uint32_t* wp = g_w   + ((size_t)(b*TS + t0)) * (TT/2);
    const uint32_t* xp = g_xsT + ((size_t)(b*DD + d0)) * (TT/2);

    // cp.async granule mapping (3 granules of 16B per thread per chunk)
    int arow = tid >> 1, ahalf = tid & 1;
    auto issue = [&](int st, int c) {
        uint32_t stg = sbase + st * STG;
        {   // A: 256 granules
            uint32_t dst = stg + arow * RSTRB + ahalf * 16;
            const uint32_t* src = wp + (size_t)arow * (TT/2) + c*8 + ahalf*4;
            asm volatile("cp.async.cg.shared.global [%0], [%1], 16;" :: "r"(dst), "l"(src));
        }
        #pragma unroll
        for (int it = 0; it < 2; it++) {   // B: 512 granules
            int idx = tid + 256 * it;
            int row = idx >> 1, half = idx & 1;
            uint32_t dst = stg + ASZ + row * RSTRB + half * 16;
            const uint32_t* src = xp + (size_t)row * (TT/2) + c*8 + half*4;
            asm volatile("cp.async.cg.shared.global [%0], [%1], 16;" :: "r"(dst), "l"(src));
        }
        asm volatile("cp.async.commit_group;" ::: "memory");
    };

    // ldmatrix per-lane address offsets
    int lr = lane & 7, q = lane >> 3;
    uint32_t aOff = (uint32_t)((wm*64 + lr + (q & 1)*8) * RSTRB + (q >> 1) * 16);
    uint32_t bOff = (uint32_t)(ASZ + (wn*64 + lr + (q >> 1)*8) * RSTRB + (q & 1) * 16);

    float acc[4][8][4];
    #pragma unroll
    for (int mt = 0; mt < 4; mt++)
        #pragma unroll
        for (int nt = 0; nt < 8; nt++)
            #pragma unroll
            for (int z = 0; z < 4; z++) acc[mt][nt][z] = 0.f;

    issue(0, 0);
    issue(1, 1);

    for (int c = 0; c < NCHUNK; c++) {
        if (c == NCHUNK - 1)
            asm volatile("cp.async.wait_group 0;" ::: "memory");
        else
            asm volatile("cp.async.wait_group 1;" ::: "memory");
        __syncthreads();

        uint32_t stg = sbase + (c % 3) * STG;
        uint32_t a[4][4];
        #pragma unroll
        for (int mt = 0; mt < 4; mt++)
            ldm_x4(a[mt], stg + aOff + mt * 16 * RSTRB);
        #pragma unroll
        for (int nt2 = 0; nt2 < 4; nt2++) {
            uint32_t bb[4];
            ldm_x4(bb, stg + bOff + nt2 * 16 * RSTRB);
            #pragma unroll
            for (int mt = 0; mt < 4; mt++) {
                mma_fp16(acc[mt][2*nt2],     a[mt], &bb[0]);
                mma_fp16(acc[mt][2*nt2 + 1], a[mt], &bb[2]);
            }
        }
        __syncthreads();
        if (c + 2 < NCHUNK) issue((c + 2) % 3, c + 2);
    }

    // Epilogue (scale folded into W)
    #pragma unroll
    for (int mt = 0; mt < 4; mt++) {
        int r0 = t0 + wm*64 + mt*16 + g;
        float* op0 = out + ((size_t)b*TS + r0) * DD + d0 + wn*64;
        float* op1 = op0 + 8 * DD;
        #pragma unroll
        for (int nt = 0; nt < 8; nt++) {
            int nn = nt*8 + tig*2;
            *(float2*)(op0 + nn) = make_float2(acc[mt][nt][0], acc[mt][nt][1]);
            *(float2*)(op1 + nn) = make_float2(acc[mt][nt][2], acc[mt][nt][3]);
        }
    }
}

// ---------------------------------------------------------------------------
// Launcher. inputs: xs f32 [B,T,D], ds i32 [B,T], sigma f32 [B,T], target i32
// output: f32 [B, 2304, D]
// ---------------------------------------------------------------------------
extern "C" void kernel_launch(void* const* d_in, const int* in_sizes, int n_in,
                              void* d_out, int out_size) {
    const float* xs    = (const float*)d_in[0];
    const int*   ds    = (const int*)  d_in[1];
    const float* sigma = (const float*)d_in[2];
    float* out = (float*)d_out;

    cudaFuncSetAttribute(lr_gemm_mma, cudaFuncAttributeMaxDynamicSharedMemorySize, DYN_SMEM);

    lr_prep_kernel<<<BB, TT>>>(ds, sigma);

    int nwarps = BB * TS;
    int nblk = (nwarps * 32 + 255) / 256;
    lr_scale_kernel<<<nblk, 256>>>();

    dim3 cg(DD / 32, TT / 32, BB);
    lr_cvtT_kernel<<<cg, dim3(32, 8)>>>(xs);

    dim3 wg(TS / 4, BB);
    lr_wgen_kernel<<<wg, 256>>>();

    dim3 grid(DD / BN, TS / BM, BB);   // (2, 18, 32)
    lr_gemm_mma<<<grid, 256, DYN_SMEM>>>(out);
}

// round 10
// speedup vs baseline: 1.1469x; 1.1469x over previous
#include <cuda_runtime.h>
#include <cuda_fp16.h>
#include <cstdint>
#include <math.h>

// Static problem shape
#define BB 32
#define TT 512
#define DD 512
#define TS 2304          // target_length - 1

#define BM 128           // t tile
#define BN 256           // d tile
#define BK 16            // k per chunk (8 kp words)
#define NCHUNK (TT/BK)   // 32

// ldmatrix row stride: 8 kp words (32B) padded to 48B (proven in round 8)
#define RSTRB 48
#define A_STAGE 6144         // 128 rows * 48B
#define B_STAGE 12288        // 256 rows * 48B
#define B_BASE  (2*A_STAGE)  // 12288
#define DYN_SMEM (B_BASE + 2*B_STAGE)   // 36864

// Device scratch
__device__ float4   g_cus[BB*TT];      // (center, -0.5*sig^2, sig, 0)
__device__ int      g_shift[BB*TT];
__device__ int      g_len[BB*TT];
__device__ float    g_scale[BB*TS];
// xs transposed+packed fp16: word(b,d,ip) = half2(xs[2ip][d], xs[2ip+1][d])
__device__ uint32_t g_xsT[(size_t)BB*DD*(TT/2)];   // 16.8 MB

__device__ __forceinline__ void mma_fp16(float* c, const uint32_t* a, const uint32_t* b) {
    asm volatile(
        "mma.sync.aligned.m16n8k16.row.col.f32.f16.f16.f32 "
        "{%0,%1,%2,%3}, {%4,%5,%6,%7}, {%8,%9}, {%0,%1,%2,%3};"
        : "+f"(c[0]), "+f"(c[1]), "+f"(c[2]), "+f"(c[3])
        : "r"(a[0]), "r"(a[1]), "r"(a[2]), "r"(a[3]), "r"(b[0]), "r"(b[1]));
}
__device__ __forceinline__ void ldm_x4(uint32_t* r, uint32_t addr) {
    asm volatile("ldmatrix.sync.aligned.m8n8.x4.shared.b16 {%0,%1,%2,%3}, [%4];"
                 : "=r"(r[0]), "=r"(r[1]), "=r"(r[2]), "=r"(r[3]) : "r"(addr));
}
__device__ __forceinline__ uint32_t smem_u32(const void* p) {
    uint32_t a;
    asm("{ .reg .u64 t; cvta.to.shared.u64 t, %1; cvt.u32.u64 %0, t; }" : "=r"(a) : "l"(p));
    return a;
}
__device__ __forceinline__ uint32_t pack_h2(float lo, float hi) {
    __half2 h = __floats2half2_rn(lo, hi);
    return *(uint32_t*)&h;
}

// ---------------------------------------------------------------------------
// Kernel 1: prep — cumsum(ds), center, sig = softplus(sigma); packs g_cus
// ---------------------------------------------------------------------------
__global__ void lr_prep_kernel(const int* __restrict__ ds,
                               const float* __restrict__ sigma) {
    __shared__ int s[TT];
    int b = blockIdx.x, t = threadIdx.x;
    int d = ds[b*TT + t];
    s[t] = d;
    __syncthreads();
    for (int off = 1; off < TT; off <<= 1) {
        int v = (t >= off) ? s[t - off] : 0;
        __syncthreads();
        s[t] += v;
        __syncthreads();
    }
    int len = s[t], sh = len - d, idx = b*TT + t;
    g_len[idx] = len;
    g_shift[idx] = sh;
    float x = sigma[idx];
    float sp = (x > 20.f) ? x : log1pf(expf(x));
    float center = 0.5f * (float)d + (float)sh;
    g_cus[idx] = make_float4(center, -0.5f * sp * sp, sp, 0.f);
}

// ---------------------------------------------------------------------------
// Kernel 2: scale[b,t] = row_mass / max(den, 1e-12)   (one warp per (b,t))
// ---------------------------------------------------------------------------
__global__ void lr_scale_kernel() {
    int warp = (blockIdx.x * blockDim.x + threadIdx.x) >> 5;
    int lane = threadIdx.x & 31;
    if (warp >= BB * TS) return;
    int b = warp / TS, t = warp % TS;
    float tr = (float)(t + 1);
    const float4* cu = g_cus + b*TT;
    const int* shp = g_shift + b*TT;
    const int* lnp = g_len + b*TT;
    float den = 0.f; int mass = 0;
    #pragma unroll 4
    for (int i = lane; i < TT; i += 32) {
        float4 u = cu[i];
        float dl = tr - u.x;
        den += __expf(u.y * dl * dl) * u.z;
        mass += (t >= shp[i] && t < lnp[i]) ? 1 : 0;
    }
    #pragma unroll
    for (int o = 16; o > 0; o >>= 1) {
        den  += __shfl_down_sync(0xffffffffu, den, o);
        mass += __shfl_down_sync(0xffffffffu, mass, o);
    }
    if (lane == 0) g_scale[warp] = (float)mass / fmaxf(den, 1e-12f);
}

// ---------------------------------------------------------------------------
// Kernel 3: xs -> g_xsT  (transpose to d-major, fp16 k-pair packed)
// ---------------------------------------------------------------------------
__global__ void lr_cvtT_kernel(const float* __restrict__ xs) {
    __shared__ float tile[32][33];
    int b = blockIdx.z;
    int dblk = blockIdx.x * 32, iblk = blockIdx.y * 32;
    int tx = threadIdx.x, ty = threadIdx.y;     // 32 x 8
    #pragma unroll
    for (int j = 0; j < 32; j += 8)
        tile[ty + j][tx] = xs[((size_t)(b*TT) + iblk + ty + j) * DD + dblk + tx];
    __syncthreads();
    int q = ty * 32 + tx;   // 0..255
    #pragma unroll
    for (int j = 0; j < 2; j++) {
        int v = q + 256 * j;          // 0..511
        int dl = v >> 4;              // 0..31
        int ip = v & 15;              // 0..15
        uint32_t w = pack_h2(tile[2*ip][dl], tile[2*ip + 1][dl]);
        g_xsT[((size_t)(b*DD) + dblk + dl) * (TT/2) + iblk/2 + ip] = w;
    }
}

// ---------------------------------------------------------------------------
// Kernel 4: GEMM. CTA 128x256, 8 warps (2x4), warp 64x64. BK=16.
// Round-6 pipeline skeleton (2-stage, genA->compute->stA->wait->sync),
// round-8 ldmatrix fragment path. Scale folded into A.
// ---------------------------------------------------------------------------
__global__ __launch_bounds__(256, 1)
void lr_gemm_mma(float* __restrict__ out) {
    extern __shared__ char sm[];
    __shared__ float4 sCU[TT];          // 8 KB static
    uint32_t sbase = smem_u32(sm);

    int tid = threadIdx.x;
    int wid = tid >> 5, lane = tid & 31;
    int g = lane >> 2, tig = lane & 3;
    int wm = wid >> 2;          // 0..1
    int wn = wid & 3;           // 0..3
    int b = blockIdx.z, t0 = blockIdx.y * BM, d0 = blockIdx.x * BN;

    const uint32_t* xp = g_xsT + ((size_t)(b*DD + d0)) * (TT/2);

    // ---- cp.async B (round-8 mapping): 256 rows x 32B; 512 granules ----
    auto cpB = [&](int st, int c) {
        #pragma unroll
        for (int it = 0; it < 2; it++) {
            int idx = tid + 256 * it;
            int row = idx >> 1, h = idx & 1;
            uint32_t dst = sbase + B_BASE + st * B_STAGE + row * RSTRB + h * 16;
            const uint32_t* src = xp + (size_t)row * (TT/2) + c*8 + h*4;
            asm volatile("cp.async.cg.shared.global [%0], [%1], 16;" :: "r"(dst), "l"(src));
        }
        asm volatile("cp.async.commit_group;" ::: "memory");
    };

    // ---- A generation (linear word layout, scale folded) ----
    int arow = tid >> 1, ah = tid & 1;
    float myscale = g_scale[b*TS + t0 + arow];
    float trow = (float)(t0 + arow + 1);
    uint32_t aNext[4];
    auto genA = [&](int c1) {
        int kb = c1 * BK;
        #pragma unroll
        for (int j = 0; j < 4; j++) {
            int w = ah*4 + j;                    // word 0..7, k = 2w, 2w+1
            float4 u0 = sCU[kb + 2*w];
            float4 u1 = sCU[kb + 2*w + 1];
            float dl0 = trow - u0.x, dl1 = trow - u1.x;
            float e0 = __expf(u0.y * dl0 * dl0) * u0.z * myscale;
            float e1 = __expf(u1.y * dl1 * dl1) * u1.z * myscale;
            aNext[j] = pack_h2(e0, e1);
        }
    };
    auto stA = [&](int st) {
        *(uint4*)(sm + st * A_STAGE + arow * RSTRB + ah * 16) = *(uint4*)aNext;
    };

    // ---- ldmatrix per-lane offsets (round-8 verified, RSTRB=48) ----
    int lr = lane & 7, q = lane >> 3;
    uint32_t aOff = (uint32_t)((wm*64 + lr + (q & 1)*8) * RSTRB + (q >> 1) * 16);
    uint32_t bOff = (uint32_t)(B_BASE + (wn*64 + lr + (q >> 1)*8) * RSTRB + (q & 1) * 16);

    float acc[4][8][4];
    #pragma unroll
    for (int mt = 0; mt < 4; mt++)
        #pragma unroll
        for (int nt = 0; nt < 8; nt++)
            #pragma unroll
            for (int z = 0; z < 4; z++) acc[mt][nt][z] = 0.f;

    // ---- prologue (round-6 ordering) ----
    cpB(0, 0);
    for (int i = tid; i < TT; i += 256) sCU[i] = g_cus[b*TT + i];
    __syncthreads();                 // sCU ready
    genA(0);
    stA(0);
    asm volatile("cp.async.wait_group 0;" ::: "memory");
    __syncthreads();

    for (int c = 0; c < NCHUNK; c++) {
        int st = c & 1;
        if (c + 1 < NCHUNK) { cpB(st ^ 1, c + 1); genA(c + 1); }

        uint32_t aBase = sbase + st * A_STAGE + aOff;
        uint32_t bBase = sbase + st * B_STAGE + bOff;
        uint32_t a[4][4];
        #pragma unroll
        for (int mt = 0; mt < 4; mt++)
            ldm_x4(a[mt], aBase + mt * 16 * RSTRB);
        #pragma unroll
        for (int nt2 = 0; nt2 < 4; nt2++) {
            uint32_t bb[4];
            ldm_x4(bb, bBase + nt2 * 16 * RSTRB);
            #pragma unroll
            for (int mt = 0; mt < 4; mt++) {
                mma_fp16(acc[mt][2*nt2],     a[mt], &bb[0]);
                mma_fp16(acc[mt][2*nt2 + 1], a[mt], &bb[2]);
            }
        }

        if (c + 1 < NCHUNK) {
            stA(st ^ 1);
            asm volatile("cp.async.wait_group 0;" ::: "memory");
        }
        __syncthreads();
    }

    // ---- epilogue (scale already folded into A) ----
    #pragma unroll
    for (int mt = 0; mt < 4; mt++) {
        int r0 = t0 + wm*64 + mt*16 + g;
        float* op0 = out + ((size_t)b*TS + r0) * DD + d0 + wn*64;
        float* op1 = op0 + 8 * DD;
        #pragma unroll
        for (int nt = 0; nt < 8; nt++) {
            int nn = nt*8 + tig*2;
            *(float2*)(op0 + nn) = make_float2(acc[mt][nt][0], acc[mt][nt][1]);
            *(float2*)(op1 + nn) = make_float2(acc[mt][nt][2], acc[mt][nt][3]);
        }
    }
}

// ---------------------------------------------------------------------------
// Launcher. inputs: xs f32 [B,T,D], ds i32 [B,T], sigma f32 [B,T], target i32
// output: f32 [B, 2304, D]
// ---------------------------------------------------------------------------
extern "C" void kernel_launch(void* const* d_in, const int* in_sizes, int n_in,
                              void* d_out, int out_size) {
    const float* xs    = (const float*)d_in[0];
    const int*   ds    = (const int*)  d_in[1];
    const float* sigma = (const float*)d_in[2];
    float* out = (float*)d_out;

    cudaFuncSetAttribute(lr_gemm_mma, cudaFuncAttributeMaxDynamicSharedMemorySize, DYN_SMEM);

    lr_prep_kernel<<<BB, TT>>>(ds, sigma);

    int nwarps = BB * TS;
    int nblk = (nwarps * 32 + 255) / 256;
    lr_scale_kernel<<<nblk, 256>>>();

    dim3 cg(DD / 32, TT / 32, BB);
    lr_cvtT_kernel<<<cg, dim3(32, 8)>>>(xs);

    dim3 grid(DD / BN, TS / BM, BB);   // (2, 18, 32)
    lr_gemm_mma<<<grid, 256, DYN_SMEM>>>(out);
}